// round 10
// baseline (speedup 1.0000x reference)
#include <cuda_runtime.h>

// knnLoss: single persistent kernel, per-warp windowed exact KNN.
// Phases (grid barriers between):
//  0 zero hists | 1 histogram(x-bin) | 2 prefix (4 blocks) | 3 counting scatter
//  4 stage A: per-warp quarter-scan of 512-target home range  -> partial top3
//  5 stage B: merge home -> per-warp window (bin-indexed) minus home, 4-way
//             index split scan with bcap pruning               -> partial top3
//  6 merge 8 partials/query (exact) + fixed-point block reduce | 7 final.

#define NPTS   16384
#define NB     2
#define NQ     (NB * NPTS)
#define NBINS  512
#define XMIN   (-4.5f)
#define BINSCL (NBINS / 9.0f)
#define NTHR   256
#define NBLK   512
#define HOME   512

__device__ int g_thist[NB * NBINS];
__device__ int g_qhist[NB * NBINS];
__device__ int g_tbase[NB * NBINS];
__device__ int g_tcur [NB * NBINS];
__device__ int g_qcur [NB * NBINS];
__device__ __align__(16) float g_sx[NQ];
__device__ __align__(16) float g_sy[NQ];
__device__ __align__(16) float g_sz[NQ];
__device__ __align__(16) float g_sw[NQ];
__device__ float4    g_q[NQ];
__device__ float     g_pA[4 * NQ * 3];
__device__ float     g_pB[4 * NQ * 3];
__device__ long long g_psum[128];
__device__ int       g_pcnt[128];
__device__ unsigned          g_barcnt;
__device__ volatile unsigned g_bargen;

#define FMA2(d, a, b, c) \
    asm("fma.rn.f32x2 %0, %1, %2, %3;" : "=l"(d) : "l"(a), "l"(b), "l"(c))
#define UNPK2(lo, hi, v) \
    asm("mov.b64 {%0, %1}, %2;" : "=f"(lo), "=f"(hi) : "l"(v))
#define PK2(d, lo, hi) \
    asm("mov.b64 %0, {%1, %2};" : "=l"(d) : "f"(lo), "f"(hi))
#define DUP2(d, f) \
    asm("mov.b64 %0, {%1, %1};" : "=l"(d) : "f"(f))

__device__ __forceinline__ void grid_sync() {
    __syncthreads();
    if (threadIdx.x == 0) {
        unsigned gen = g_bargen;
        __threadfence();
        unsigned rank = atomicAdd(&g_barcnt, 1u);
        if (rank == NBLK - 1) {
            g_barcnt = 0;
            __threadfence();
            g_bargen = gen + 1;
        } else {
            while (g_bargen == gen) { __nanosleep(128); }
        }
        __threadfence();
    }
    __syncthreads();
}

__device__ __forceinline__ int xbin(float x) {
    int b = (int)((x - XMIN) * BINSCL);
    return min(max(b, 0), NBINS - 1);
}

__device__ __forceinline__ void top3_insert(float r, float& b0, float& b1, float& b2) {
    float m1 = fmaxf(r, b1);
    float m0 = fmaxf(r, b0);
    b2 = fminf(b2, m1);
    b1 = fminf(b1, m0);
    b0 = fminf(b0, r);
}

// warp-cooperative scan of [beg, beg+4*ng) targets (beg 4-aligned, warp-uniform).
// Each lane keeps its own query's top3 in r-space; skip gated by warp-any.
__device__ __forceinline__ void scan_warp(
    const float* __restrict__ sx, const float* __restrict__ sy,
    const float* __restrict__ sz, const float* __restrict__ sw,
    int beg, int ng,
    unsigned long long qx, unsigned long long qy, unsigned long long qz,
    float& b0, float& b1, float& b2, float& bcap)
{
#pragma unroll 2
    for (int g = 0; g < ng; g++) {
        int idx = beg + 4 * g;
        float4 xv = __ldg((const float4*)(sx + idx));
        float4 yv = __ldg((const float4*)(sy + idx));
        float4 zv = __ldg((const float4*)(sz + idx));
        float4 wv = __ldg((const float4*)(sw + idx));
        unsigned long long xp0, xp1, yp0, yp1, zp0, zp1, wp0, wp1;
        PK2(xp0, xv.x, xv.y); PK2(xp1, xv.z, xv.w);
        PK2(yp0, yv.x, yv.y); PK2(yp1, yv.z, yv.w);
        PK2(zp0, zv.x, zv.y); PK2(zp1, zv.z, zv.w);
        PK2(wp0, wv.x, wv.y); PK2(wp1, wv.z, wv.w);
        unsigned long long rA, rB;
        FMA2(rA, qx, xp0, wp0);
        FMA2(rB, qx, xp1, wp1);
        FMA2(rA, qy, yp0, rA);
        FMA2(rB, qy, yp1, rB);
        FMA2(rA, qz, zp0, rA);
        FMA2(rB, qz, zp1, rB);
        float r0, r1, r2, r3;
        UNPK2(r0, r1, rA);
        UNPK2(r2, r3, rB);
        float m = fminf(fminf(r0, r1), fminf(r2, r3));
        if (__any_sync(0xffffffffu, m < bcap)) {
            top3_insert(r0, b0, b1, b2);
            top3_insert(r1, b0, b1, b2);
            top3_insert(r2, b0, b1, b2);
            top3_insert(r3, b0, b1, b2);
            bcap = fminf(bcap, b2);
        }
    }
}

__global__ __launch_bounds__(NTHR, 4) void fused_kernel(
    const float* __restrict__ src, const float* __restrict__ tgt,
    float* __restrict__ out)
{
    __shared__ int       scan[NBINS];
    __shared__ long long wsum[NTHR / 32];
    __shared__ int       wcnt[NTHR / 32];
    __shared__ long long rs[128];
    __shared__ int       rc[128];

    int tid  = threadIdx.x;
    int bid  = blockIdx.x;
    int gi   = bid * NTHR + tid;
    int lane = tid & 31;
    int gw   = gi >> 5;            // global warp 0..4095
    int qg   = gw >> 2;            // query group (32 queries) 0..1023
    int sp   = gw & 3;             // split id
    int b    = qg >> 9;            // batch
    int qid  = b * NPTS + (qg & 511) * 32 + lane;

    // ---- phase 0: zero histograms ----
    if (gi < NB * NBINS)           g_thist[gi] = 0;
    else if (gi < 2 * NB * NBINS)  g_qhist[gi - NB * NBINS] = 0;
    grid_sync();

    // input decode (phases 1 & 3) — ONLY meaningful for gi < NB*NPTS
    int pb = gi >> 14;
    int pn = gi & (NPTS - 1);
    int ph = pn >> 9;
    int pw = pn & 511;
    long sOff = (((long)pb * 64 + 2 * ph) * 2048 + 4 * pw) * 3;
    long tOff = (long)pb * 3 * 64 * 2048 + (long)(2 * ph) * 2048 + 4 * pw;

    // ---- phase 1: histogram ----
    if (gi < NB * NPTS) {
        float sxv = src[sOff];
        float txv = tgt[tOff];
        atomicAdd(&g_thist[pb * NBINS + xbin(txv)], 1);
        atomicAdd(&g_qhist[pb * NBINS + xbin(sxv)], 1);
    }
    grid_sync();

    // ---- phase 2: prefix sums, one array per block 0..3 ----
    if (bid < 4) {
        const int* h = (bid < 2) ? (g_thist + bid * NBINS)
                                 : (g_qhist + (bid - 2) * NBINS);
        int o0 = __ldcg(h + tid);
        int o1 = __ldcg(h + tid + NTHR);
        scan[tid] = o0;
        scan[tid + NTHR] = o1;
        __syncthreads();
        for (int off = 1; off < NBINS; off <<= 1) {
            int v0 = (tid >= off) ? scan[tid - off] : 0;
            int v1 = (tid + NTHR >= off) ? scan[tid + NTHR - off] : 0;
            __syncthreads();
            scan[tid] += v0;
            scan[tid + NTHR] += v1;
            __syncthreads();
        }
        int e0 = scan[tid] - o0;
        int e1 = scan[tid + NTHR] - o1;
        if (bid < 2) {
            g_tbase[bid * NBINS + tid] = e0;
            g_tbase[bid * NBINS + tid + NTHR] = e1;
            g_tcur [bid * NBINS + tid] = e0;
            g_tcur [bid * NBINS + tid + NTHR] = e1;
        } else {
            g_qcur[(bid - 2) * NBINS + tid] = e0;
            g_qcur[(bid - 2) * NBINS + tid + NTHR] = e1;
        }
    }
    grid_sync();

    // ---- phase 3: counting scatter ----
    if (gi < NB * NPTS) {
        float tx = tgt[tOff];
        float ty = tgt[tOff + 64 * 2048];
        float tz = tgt[tOff + 2L * 64 * 2048];
        bool  vt = (tx != 0.0f) || (ty != 0.0f) || (tz != 0.0f);
        float tw;
        if (vt) tw = tx * tx + ty * ty + tz * tz;
        else { tx = 0.0f; ty = 0.0f; tz = 0.0f; tw = 1e20f; }
        int tpos = atomicAdd(&g_tcur[pb * NBINS + xbin(tx)], 1);
        int ts = pb * NPTS + tpos;
        g_sx[ts] = tx; g_sy[ts] = ty; g_sz[ts] = tz; g_sw[ts] = tw;

        float sxv = src[sOff + 0];
        float syv = src[sOff + 1];
        float szv = src[sOff + 2];
        bool  vs = (sxv != 0.0f) || (syv != 0.0f) || (szv != 0.0f);
        float sq2 = sxv * sxv + syv * syv + szv * szv;
        int qpos = atomicAdd(&g_qcur[pb * NBINS + xbin(sxv)], 1);
        g_q[pb * NPTS + qpos] = make_float4(-2.0f * sxv, -2.0f * syv, -2.0f * szv,
                                            vs ? sq2 : -1.0f);
    }
    grid_sync();

    // per-query state
    float4 s  = g_q[qid];
    float  xq = -0.5f * s.x;
    bool   valid = (s.w >= 0.0f);
    float  sq = fmaxf(s.w, 0.0f);
    unsigned long long qx, qy, qz;
    DUP2(qx, s.x); DUP2(qy, s.y); DUP2(qz, s.z);

    const float* sxp = g_sx + b * NPTS;
    const float* syp = g_sy + b * NPTS;
    const float* szp = g_sz + b * NPTS;
    const float* swp = g_sw + b * NPTS;

    // warp-uniform home range (512 targets, 4-aligned, deterministic)
    float x15 = __shfl_sync(0xffffffffu, xq, 15);
    int  pos  = g_tbase[b * NBINS + xbin(x15)];
    int  hLo  = (pos - HOME / 2) & ~3;
    hLo = max(0, min(hLo, NPTS - HOME));
    int  hHi  = hLo + HOME;

    // ---- phase 4 (stage A): quarter-scan of home range ----
    {
        float b0 = 3e38f, b1 = 3e38f, b2 = 3e38f, bcap = 3e38f;
        scan_warp(sxp, syp, szp, swp, hLo + sp * (HOME / 4), HOME / 16,
                  qx, qy, qz, b0, b1, b2, bcap);
        int o = (sp * NQ + qid) * 3;
        g_pA[o + 0] = b0;
        g_pA[o + 1] = b1;
        g_pA[o + 2] = b2;
    }
    grid_sync();

    // ---- phase 5 (stage B): per-warp window minus home, 4-way index split ----
    {
        float h0 = 3e38f, h1 = 3e38f, h2 = 3e38f;
#pragma unroll
        for (int k = 0; k < 4; k++) {
            int o = (k * NQ + qid) * 3;
            top3_insert(__ldcg(&g_pA[o + 0]), h0, h1, h2);
            top3_insert(__ldcg(&g_pA[o + 1]), h0, h1, h2);
            top3_insert(__ldcg(&g_pA[o + 2]), h0, h1, h2);
        }
        float rq = sqrtf(fmaxf(h2 + sq, 0.0f));
        float Am = valid ? xq - rq :  1e30f;
        float Bm = valid ? xq + rq : -1e30f;
#pragma unroll
        for (int o = 16; o; o >>= 1) {
            Am = fminf(Am, __shfl_xor_sync(0xffffffffu, Am, o));
            Bm = fmaxf(Bm, __shfl_xor_sync(0xffffffffu, Bm, o));
        }

        float b0 = 3e38f, b1 = 3e38f, b2 = 3e38f;
        float bcap = h2;

        if (Am <= Bm) {
            int binA = xbin(Am);
            int binB = xbin(Bm);
            int wLo  = g_tbase[b * NBINS + binA] & ~3;
            int wHi  = (binB >= NBINS - 1) ? NPTS
                       : ((g_tbase[b * NBINS + binB + 1] + 3) & ~3);
            wHi = min(wHi, NPTS);

            int lEnd = min(hLo, wHi);
            int gL   = max(0, (lEnd - wLo) >> 2);
            int rLo  = max(hHi, wLo);
            int gR   = max(0, (wHi - rLo) >> 2);
            int gTot = gL + gR;

            int gb = (sp * gTot) >> 2;
            int ge = ((sp + 1) * gTot) >> 2;

            int l0 = gb, l1 = min(ge, gL);
            if (l1 > l0)
                scan_warp(sxp, syp, szp, swp, wLo + 4 * l0, l1 - l0,
                          qx, qy, qz, b0, b1, b2, bcap);
            int r0 = max(gb, gL), r1 = ge;
            if (r1 > r0)
                scan_warp(sxp, syp, szp, swp, rLo + 4 * (r0 - gL), r1 - r0,
                          qx, qy, qz, b0, b1, b2, bcap);
        }
        int o = (sp * NQ + qid) * 3;
        g_pB[o + 0] = b0;
        g_pB[o + 1] = b1;
        g_pB[o + 2] = b2;
    }
    grid_sync();

    // ---- phase 6: merge 8 partials/query + fixed-point block reduce ----
    if (bid < 128) {
        int mqg  = gw;                       // blocks 0..127 -> qg = gw (0..1023)
        int mb   = mqg >> 9;
        int mqid = mb * NPTS + (mqg & 511) * 32 + lane;

        float4 ms = g_q[mqid];
        bool  mvalid = (ms.w >= 0.0f);
        float msq = fmaxf(ms.w, 0.0f);

        float b0 = 3e38f, b1 = 3e38f, b2 = 3e38f;
#pragma unroll
        for (int k = 0; k < 4; k++) {
            int oa = (k * NQ + mqid) * 3;
            top3_insert(__ldcg(&g_pA[oa + 0]), b0, b1, b2);
            top3_insert(__ldcg(&g_pA[oa + 1]), b0, b1, b2);
            top3_insert(__ldcg(&g_pA[oa + 2]), b0, b1, b2);
            top3_insert(__ldcg(&g_pB[oa + 0]), b0, b1, b2);
            top3_insert(__ldcg(&g_pB[oa + 1]), b0, b1, b2);
            top3_insert(__ldcg(&g_pB[oa + 2]), b0, b1, b2);
        }
        float wgt  = mvalid ? 1.0f : 0.0f;
        float dsum = sqrtf(fmaxf(b0 + msq, 0.0f))
                   + sqrtf(fmaxf(b1 + msq, 0.0f))
                   + sqrtf(fmaxf(b2 + msq, 0.0f));
        long long v = __float2ll_rn(fminf(wgt * dsum, 1e5f) * 4294967296.0f);
#pragma unroll
        for (int o = 16; o; o >>= 1)
            v += __shfl_down_sync(0xffffffffu, v, o);
        int cnt = __popc(__ballot_sync(0xffffffffu, mvalid));
        int warp = tid >> 5;
        if (lane == 0) { wsum[warp] = v; wcnt[warp] = cnt; }
        __syncthreads();
        if (tid == 0) {
            long long vs = 0; int cs = 0;
#pragma unroll
            for (int i = 0; i < NTHR / 32; i++) { vs += wsum[i]; cs += wcnt[i]; }
            g_psum[bid] = vs;
            g_pcnt[bid] = cs;
        }
    }
    grid_sync();

    // ---- phase 7: final reduce (block 0; [0,64)=batch0, [64,128)=batch1) ----
    if (bid == 0) {
        if (tid < 128) {
            rs[tid] = __ldcg(&g_psum[tid]);
            rc[tid] = __ldcg(&g_pcnt[tid]);
        }
        __syncthreads();
        for (int o = 32; o; o >>= 1) {
            if (tid < o) { rs[tid] += rs[tid + o]; rc[tid] += rc[tid + o]; }
            else if (tid >= 64 && tid < 64 + o) {
                rs[tid] += rs[tid + o]; rc[tid] += rc[tid + o];
            }
            __syncthreads();
        }
        if (tid == 0) {
            double S0 = (double)rs[0]  / 4294967296.0;
            double S1 = (double)rs[64] / 4294967296.0;
            float l0 = (float)(S0 / (3.0 * (double)max(rc[0],  1)));
            float l1 = (float)(S1 / (3.0 * (double)max(rc[64], 1)));
            out[0] = 0.5f * (l0 + l1);
        }
    }
}

extern "C" void kernel_launch(void* const* d_in, const int* in_sizes, int n_in,
                              void* d_out, int out_size) {
    const float* src = (const float*)d_in[0];   // source_pc [2,64,2048,3]
    const float* tgt = (const float*)d_in[1];   // target_pc [2,3,64,2048]
    fused_kernel<<<NBLK, NTHR>>>(src, tgt, (float*)d_out);
}